// round 15
// baseline (speedup 1.0000x reference)
#include <cuda_runtime.h>
#include <cuda_bf16.h>
#include <math.h>

// Problem constants (fixed by the reference)
#define N_DIM 8192
#define E_CNT 262144
#define EPS 1e-8f

#define THREADS 256
#define BLOCKS  512
#define NBIN    8192          // one bin per adjacency row (32 KB region)
#define BIN_CAP 112           // mean 64/bin, sigma~8 -> 6 sigma slack
#define OF_CAP  8192          // overflow safety net

// Scratch (no cudaMalloc allowed). g_cnt/g_of_cnt/g_ticket are zero at load
// and re-zeroed by the last block of gather_kernel each run -> graph-replay
// safe with no init launch.
__device__ unsigned int g_cnt[NBIN];
__device__ unsigned int g_items[NBIN * BIN_CAP];   // 3.67 MB packed items
__device__ unsigned int g_of_items[OF_CAP];
__device__ unsigned int g_of_cnt;
__device__ float g_part_pos[BLOCKS];
__device__ float g_part_neg[BLOCKS];
__device__ unsigned int g_ticket;

// item pack: bits[14..26]=row, bits[1..13]=col, bit0 = is_negative
__device__ __forceinline__ void put_item(int row, int col, unsigned flag) {
    unsigned pack = ((unsigned)row << 14) | ((unsigned)col << 1) | flag;
    unsigned pos = atomicAdd(&g_cnt[row], 1u);
    if (pos < BIN_CAP) {
        g_items[row * BIN_CAP + pos] = pack;
    } else {
        unsigned o = atomicAdd(&g_of_cnt, 1u);
        if (o < OF_CAP) g_of_items[o] = pack;
    }
}

// K1: bin all edges by adjacency row (coalesced index reads, spread atomics)
__global__ __launch_bounds__(THREADS) void scatter_kernel(
    const int* __restrict__ edge_index,   // [2, E]: src then dst
    const int* __restrict__ neg_edges)    // [E, 2] interleaved
{
    const int t = blockIdx.x * THREADS + threadIdx.x;   // 0 .. E/2-1
    const int i = 2 * t;

    int2 src2 = __ldg((const int2*)&edge_index[i]);
    int2 dst2 = __ldg((const int2*)&edge_index[E_CNT + i]);
    int4 neg4 = __ldg((const int4*)&neg_edges[2 * i]);

    put_item(src2.x, dst2.x, 0u);
    put_item(src2.y, dst2.y, 0u);
    put_item(neg4.x, neg4.y, 1u);
    put_item(neg4.z, neg4.w, 1u);
}

// K2: each warp processes 2 row-bins -> gathers cluster inside 32 KB windows.
// Last block (ticket) handles overflow, final reduce, epilogue, counter reset.
__global__ __launch_bounds__(THREADS) void gather_kernel(
    const float* __restrict__ adj,
    const float* __restrict__ codebook,
    float* __restrict__ out)
{
    const int lane = threadIdx.x & 31;
    const int wid  = threadIdx.x >> 5;
    const int bin0 = blockIdx.x * 16 + wid * 2;   // 512 blocks * 16 bins = 8192

    const unsigned cnt0 = min(g_cnt[bin0],     (unsigned)BIN_CAP);
    const unsigned cnt1 = min(g_cnt[bin0 + 1], (unsigned)BIN_CAP);

    unsigned items[8];
    float    vals[8];
    bool     ok[8];
    #pragma unroll
    for (int k = 0; k < 4; k++) {
        unsigned idx = (unsigned)lane + 32u * k;
        ok[k]     = idx < cnt0;
        items[k]  = ok[k] ? g_items[bin0 * BIN_CAP + idx] : 0u;
        ok[4+k]   = idx < cnt1;
        items[4+k]= ok[4+k] ? g_items[(bin0 + 1) * BIN_CAP + idx] : 0u;
    }
    #pragma unroll
    for (int k = 0; k < 8; k++) {
        if (ok[k]) {
            int row = (int)(items[k] >> 14);
            int col = (int)((items[k] >> 1) & 0x1FFFu);
            vals[k] = __ldg(&adj[(long long)row * N_DIM + col]);
        }
    }
    float pos_acc = 0.0f, neg_acc = 0.0f;
    #pragma unroll
    for (int k = 0; k < 8; k++) {
        if (ok[k]) {
            if (items[k] & 1u) neg_acc += __logf(1.0f - vals[k] + EPS);
            else               pos_acc += __logf(vals[k] + EPS);
        }
    }

    // ---- block reduction ----
    #pragma unroll
    for (int off = 16; off > 0; off >>= 1) {
        pos_acc += __shfl_down_sync(0xFFFFFFFFu, pos_acc, off);
        neg_acc += __shfl_down_sync(0xFFFFFFFFu, neg_acc, off);
    }
    __shared__ float s_pos[8];
    __shared__ float s_neg[8];
    __shared__ bool  s_is_last;
    if (lane == 0) { s_pos[wid] = pos_acc; s_neg[wid] = neg_acc; }
    __syncthreads();

    if (wid == 0) {
        float p = (lane < 8) ? s_pos[lane] : 0.0f;
        float n = (lane < 8) ? s_neg[lane] : 0.0f;
        #pragma unroll
        for (int off = 4; off > 0; off >>= 1) {
            p += __shfl_down_sync(0xFFFFFFFFu, p, off);
            n += __shfl_down_sync(0xFFFFFFFFu, n, off);
        }
        if (lane == 0) {
            g_part_pos[blockIdx.x] = p;
            g_part_neg[blockIdx.x] = n;
            __threadfence();
            unsigned ticket = atomicInc(&g_ticket, BLOCKS - 1);
            s_is_last = (ticket == BLOCKS - 1);
        }
    }
    __syncthreads();

    if (s_is_last) {
        __threadfence();
        // overflow items (normally zero)
        float op = 0.0f, on = 0.0f;
        unsigned nof = min(g_of_cnt, (unsigned)OF_CAP);
        for (unsigned j = threadIdx.x; j < nof; j += THREADS) {
            unsigned it = g_of_items[j];
            int row = (int)(it >> 14);
            int col = (int)((it >> 1) & 0x1FFFu);
            float v = __ldg(&adj[(long long)row * N_DIM + col]);
            if (it & 1u) on += __logf(1.0f - v + EPS);
            else         op += __logf(v + EPS);
        }
        float p = g_part_pos[threadIdx.x] + g_part_pos[threadIdx.x + THREADS] + op;
        float n = g_part_neg[threadIdx.x] + g_part_neg[threadIdx.x + THREADS] + on;

        #pragma unroll
        for (int off = 16; off > 0; off >>= 1) {
            p += __shfl_down_sync(0xFFFFFFFFu, p, off);
            n += __shfl_down_sync(0xFFFFFFFFu, n, off);
        }
        if (lane == 0) { s_pos[wid] = p; s_neg[wid] = n; }
        __syncthreads();
        if (wid == 0) {
            float pp = (lane < 8) ? s_pos[lane] : 0.0f;
            float nn = (lane < 8) ? s_neg[lane] : 0.0f;
            #pragma unroll
            for (int off = 4; off > 0; off >>= 1) {
                pp += __shfl_down_sync(0xFFFFFFFFu, pp, off);
                nn += __shfl_down_sync(0xFFFFFFFFu, nn, off);
            }
            if (lane == 0) {
                out[0] = -(pp + nn) * (1.0f / (float)E_CNT)
                       + codebook[0] + codebook[1] + codebook[2] + codebook[3];
            }
        }
        __syncthreads();
        // reset scratch for next graph replay (all reads of g_cnt are done:
        // every block passed its ticket)
        for (int j = threadIdx.x; j < NBIN; j += THREADS) g_cnt[j] = 0u;
        if (threadIdx.x == 0) { g_of_cnt = 0u; g_ticket = 0u; }
    }
}

extern "C" void kernel_launch(void* const* d_in, const int* in_sizes, int n_in,
                              void* d_out, int out_size) {
    const float* adj       = (const float*)d_in[0];   // [8192, 8192] f32
    const float* codebook  = (const float*)d_in[1];   // [6] f32
    const int*   edge_idx  = (const int*)d_in[2];     // [2, E] i32
    const int*   neg_edges = (const int*)d_in[3];     // [E, 2] i32
    float*       out       = (float*)d_out;

    scatter_kernel<<<BLOCKS, THREADS>>>(edge_idx, neg_edges);
    gather_kernel<<<BLOCKS, THREADS>>>(adj, codebook, out);
}